// round 9
// baseline (speedup 1.0000x reference)
#include <cuda_runtime.h>
#include <cstdint>

#define HH 64
#define NN 512
#define BB 128
#define SCALE 0.125f

__device__ float g_qp[BB * NN * HH];
__device__ float g_kp[BB * NN * HH];
__device__ float g_vp[BB * NN * HH];

// ---------------- helpers ----------------
__device__ __forceinline__ uint32_t tf32r(float f) {
    uint32_t u;
    asm("cvt.rna.tf32.f32 %0, %1;" : "=r"(u) : "f"(f));
    return u;
}
__device__ __forceinline__ void mma_tf32(float* d, const uint32_t* a,
                                         uint32_t b0, uint32_t b1) {
    asm volatile(
        "mma.sync.aligned.m16n8k8.row.col.f32.tf32.tf32.f32 "
        "{%0,%1,%2,%3}, {%4,%5,%6,%7}, {%8,%9}, {%0,%1,%2,%3};"
        : "+f"(d[0]), "+f"(d[1]), "+f"(d[2]), "+f"(d[3])
        : "r"(a[0]), "r"(a[1]), "r"(a[2]), "r"(a[3]), "r"(b0), "r"(b1));
}

// exp(s * 0.125) on FMA/ALU pipes only.
__device__ __forceinline__ float fexp8(float s) {
    float y = s * 0.18033688011112042f;      // 0.125 * log2(e)
    float z = y + 12582912.0f;               // RN to integer
    int   i = __float_as_int(z) - 0x4B400000;
    float f = y - (z - 12582912.0f);
    float p = 0.0013333558f;
    p = p * f + 0.0096181291f;
    p = p * f + 0.0555041087f;
    p = p * f + 0.2402265070f;
    p = p * f + 0.6931471806f;
    p = p * f + 1.0f;
    return __int_as_float(__float_as_int(p) + (i << 23));
}

// ---------------------------------------------------------------------------
// Projection with tf32 mma; outputs stored tf32-pre-rounded (rna).
// ---------------------------------------------------------------------------
__global__ __launch_bounds__(256, 2) void proj_kernel(
    const float* __restrict__ q, const float* __restrict__ k,
    const float* __restrict__ v,
    const float* __restrict__ Wq, const float* __restrict__ bq,
    const float* __restrict__ Wk, const float* __restrict__ bk,
    const float* __restrict__ Wv, const float* __restrict__ bv)
{
    __shared__ uint32_t sX[128 * 68];
    __shared__ uint32_t sW[64 * 68];
    __shared__ float    sB[64];

    const float* x; const float* W; const float* bias; float* dst;
    if (blockIdx.y == 0)      { x = q; W = Wq; bias = bq; dst = g_qp; }
    else if (blockIdx.y == 1) { x = k; W = Wk; bias = bk; dst = g_kp; }
    else                      { x = v; W = Wv; bias = bv; dst = g_vp; }

    const int tid  = threadIdx.x;
    const int row0 = blockIdx.x * 128;

    #pragma unroll
    for (int it = 0; it < 8; it++) {
        int idx = tid + it * 256;
        int r = idx >> 4, c4 = idx & 15;
        float4 t = *reinterpret_cast<const float4*>(x + (size_t)(row0 + r) * HH + c4 * 4);
        uint4 u = { tf32r(t.x), tf32r(t.y), tf32r(t.z), tf32r(t.w) };
        *reinterpret_cast<uint4*>(&sX[r * 68 + c4 * 4]) = u;
    }
    #pragma unroll
    for (int it = 0; it < 4; it++) {
        int idx = tid + it * 256;
        int r = idx >> 4, c4 = idx & 15;
        float4 t = *reinterpret_cast<const float4*>(W + (size_t)r * HH + c4 * 4);
        uint4 u = { tf32r(t.x), tf32r(t.y), tf32r(t.z), tf32r(t.w) };
        *reinterpret_cast<uint4*>(&sW[r * 68 + c4 * 4]) = u;
    }
    if (tid < 64) sB[tid] = bias[tid];
    __syncthreads();

    const int w    = tid >> 5;
    const int lane = tid & 31;
    const int lx   = lane & 3;
    const int ly   = lane >> 2;
    const int r0   = w * 16 + ly;
    const int r1   = r0 + 8;

    float acc[8][4];
    #pragma unroll
    for (int t = 0; t < 8; t++)
        #pragma unroll
        for (int i = 0; i < 4; i++) acc[t][i] = 0.f;

    #pragma unroll
    for (int k0 = 0; k0 < 64; k0 += 8) {
        uint32_t a[4];
        a[0] = sX[r0 * 68 + k0 + lx];
        a[1] = sX[r1 * 68 + k0 + lx];
        a[2] = sX[r0 * 68 + k0 + lx + 4];
        a[3] = sX[r1 * 68 + k0 + lx + 4];
        #pragma unroll
        for (int t = 0; t < 8; t++) {
            uint32_t b0 = sW[(t * 8 + ly) * 68 + k0 + lx];
            uint32_t b1 = sW[(t * 8 + ly) * 68 + k0 + 4 + lx];
            mma_tf32(acc[t], a, b0, b1);
        }
    }

    int g0 = row0 + r0, g1 = row0 + r1;
    float* orow0 = dst + ((size_t)(g0 & 127) * NN + (g0 >> 7)) * HH;
    float* orow1 = dst + ((size_t)(g1 & 127) * NN + (g1 >> 7)) * HH;
    #pragma unroll
    for (int t = 0; t < 8; t++) {
        int c0 = t * 8 + 2 * lx;
        float b0 = sB[c0], b1 = sB[c0 + 1];
        float2 o0 = make_float2(__uint_as_float(tf32r(acc[t][0] + b0)),
                                __uint_as_float(tf32r(acc[t][1] + b1)));
        float2 o1 = make_float2(__uint_as_float(tf32r(acc[t][2] + b0)),
                                __uint_as_float(tf32r(acc[t][3] + b1)));
        *reinterpret_cast<float2*>(orow0 + c0) = o0;
        *reinterpret_cast<float2*>(orow1 + c0) = o1;
    }
}

// ---------------------------------------------------------------------------
// Attention: CTA = 64 n-rows x one batch, 512 threads (16 warps =
// 4 row-stripes x 4 col-quads), 4 chunks of 128 keys.
// AV via out^T = V^T e^T : e B-frags built by warp shuffles from S C-frags;
// per-quad partial out^T reduced through smem once at the end.
// ---------------------------------------------------------------------------
// smem float offsets
#define OQ   0                      // 64 x 68
#define OK_  4352                   // 128 x 68 (reused as out^T stage: 4 x 64 x 68)
#define OV   13056                  // 128 x 72
#define OA   22272                  // 64 x 516 (e for A output; write-only in loop)
#define OS   55296                  // 256 partial row sums
#define OI   55552                  // 64 inverse sums
#define SMEM_FLOATS 55616

__global__ __launch_bounds__(512, 1) void attn_kernel(
    const float* __restrict__ mask,
    float* __restrict__ out,     // [N,B,H]
    float* __restrict__ Aout)    // [B,N,N]
{
    extern __shared__ float sm[];
    float*    sAf = sm + OA;
    uint32_t* sQu = reinterpret_cast<uint32_t*>(sm + OQ);
    uint32_t* sKu = reinterpret_cast<uint32_t*>(sm + OK_);
    uint32_t* sVu = reinterpret_cast<uint32_t*>(sm + OV);

    const int tid  = threadIdx.x;
    const int w    = tid >> 5;
    const int lane = tid & 31;
    const int lx   = lane & 3;
    const int ly   = lane >> 2;
    const int stripe = w & 3;        // 16-row stripe (0..3)
    const int quad   = w >> 2;       // key group (0..3)
    const int r0 = stripe * 16 + ly, r1 = r0 + 8;

    const int n0 = blockIdx.x * 64;
    const int b  = blockIdx.y;

    const float* qp = g_qp + (size_t)b * NN * HH;
    const float* kp = g_kp + (size_t)b * NN * HH;
    const float* vp = g_vp + (size_t)b * NN * HH;
    const float* mbase = mask + ((size_t)b * NN + n0) * NN;

    // shuffle source lanes for e^T B-frag construction
    const int l0 = ly * 4 + (lx >> 1);
    const int l1 = l0 + 2;
    const bool oddx = (lx & 1);

    // ---- Q tile (64 x 64), already tf32-rounded by proj
    #pragma unroll
    for (int it = 0; it < 2; it++) {
        int idx = tid + it * 512;
        int r = idx >> 4, c4 = idx & 15;
        float4 t = *reinterpret_cast<const float4*>(qp + (size_t)(n0 + r) * HH + c4 * 4);
        *reinterpret_cast<float4*>(&sm[OQ + r * 68 + c4 * 4]) = t;
    }
    __syncthreads();

    // ---- Q fragments hoisted
    uint32_t qf[8][4];
    #pragma unroll
    for (int kk = 0; kk < 8; kk++) {
        int k0 = kk * 8;
        qf[kk][0] = sQu[r0 * 68 + k0 + lx];
        qf[kk][1] = sQu[r1 * 68 + k0 + lx];
        qf[kk][2] = sQu[r0 * 68 + k0 + lx + 4];
        qf[kk][3] = sQu[r1 * 68 + k0 + lx + 4];
    }

    // out^T partial accumulators: [hg 0..3][rg 0..1] -> oacc[hg*2+rg][4]
    float oacc[8][4];
    #pragma unroll
    for (int t = 0; t < 8; t++)
        #pragma unroll
        for (int i = 0; i < 4; i++) oacc[t][i] = 0.f;
    float rsum0 = 0.f, rsum1 = 0.f;

    for (int c = 0; c < 4; c++) {
        const int mt = c * 128;
        __syncthreads();   // all warps done with prev sK/sV

        // ---- load K/V chunk (128 x 64 each)
        #pragma unroll
        for (int it = 0; it < 4; it++) {
            int idx = tid + it * 512;
            int r = idx >> 4, c4 = idx & 15;
            float4 t = *reinterpret_cast<const float4*>(kp + (size_t)(mt + r) * HH + c4 * 4);
            *reinterpret_cast<float4*>(&sm[OK_ + r * 68 + c4 * 4]) = t;
            float4 s = *reinterpret_cast<const float4*>(vp + (size_t)(mt + r) * HH + c4 * 4);
            *reinterpret_cast<float4*>(&sm[OV + r * 72 + c4 * 4]) = s;
        }
        __syncthreads();

        // ---- mask loads early
        float2 m0[4], m1[4];
        #pragma unroll
        for (int t = 0; t < 4; t++) {
            int gc = mt + quad * 32 + t * 8 + 2 * lx;
            m0[t] = *reinterpret_cast<const float2*>(mbase + (size_t)r0 * NN + gc);
            m1[t] = *reinterpret_cast<const float2*>(mbase + (size_t)r1 * NN + gc);
        }

        // ---- S = Q K^T : 16 rows x 32 keys per warp
        float sacc[4][4];
        #pragma unroll
        for (int t = 0; t < 4; t++)
            #pragma unroll
            for (int i = 0; i < 4; i++) sacc[t][i] = 0.f;

        #pragma unroll
        for (int kk = 0; kk < 8; kk++) {
            int k0 = kk * 8;
            #pragma unroll
            for (int t = 0; t < 4; t++) {
                int key = quad * 32 + t * 8 + ly;
                uint32_t b0 = sKu[key * 68 + k0 + lx];
                uint32_t b1 = sKu[key * 68 + k0 + 4 + lx];
                mma_tf32(sacc[t], qf[kk], b0, b1);
            }
        }

        // ---- e = exp(S/8)*mask in C-frag registers; rowsums; e -> sA (A out)
        #pragma unroll
        for (int t = 0; t < 4; t++) {
            int gc = mt + quad * 32 + t * 8 + 2 * lx;
            float e00 = fexp8(sacc[t][0]) * m0[t].x;
            float e01 = fexp8(sacc[t][1]) * m0[t].y;
            float e10 = fexp8(sacc[t][2]) * m1[t].x;
            float e11 = fexp8(sacc[t][3]) * m1[t].y;
            rsum0 += e00 + e01;
            rsum1 += e10 + e11;
            *reinterpret_cast<float2*>(&sAf[r0 * 516 + gc]) = make_float2(e00, e01);
            *reinterpret_cast<float2*>(&sAf[r1 * 516 + gc]) = make_float2(e10, e11);
            sacc[t][0] = e00; sacc[t][1] = e01; sacc[t][2] = e10; sacc[t][3] = e11;
        }

        // ---- AV: out^T += V^T e^T, warp-local (no barrier needed)
        #pragma unroll
        for (int kt = 0; kt < 4; kt++) {
            // e^T B-frags via shuffles: rg0 (rows ly of stripe), rg1 (rows ly+8)
            float t00 = __shfl_sync(0xffffffffu, sacc[kt][0], l0);
            float t01 = __shfl_sync(0xffffffffu, sacc[kt][1], l0);
            float t10 = __shfl_sync(0xffffffffu, sacc[kt][0], l1);
            float t11 = __shfl_sync(0xffffffffu, sacc[kt][1], l1);
            uint32_t b0_rg0 = __float_as_uint(oddx ? t01 : t00);
            uint32_t b1_rg0 = __float_as_uint(oddx ? t11 : t10);
            float u00 = __shfl_sync(0xffffffffu, sacc[kt][2], l0);
            float u01 = __shfl_sync(0xffffffffu, sacc[kt][3], l0);
            float u10 = __shfl_sync(0xffffffffu, sacc[kt][2], l1);
            float u11 = __shfl_sync(0xffffffffu, sacc[kt][3], l1);
            uint32_t b0_rg1 = __float_as_uint(oddx ? u01 : u00);
            uint32_t b1_rg1 = __float_as_uint(oddx ? u11 : u10);

            const int kbase = mt - mt + quad * 32 + kt * 8;  // within-chunk key base
            #pragma unroll
            for (int hg = 0; hg < 4; hg++) {
                uint32_t a[4];
                a[0] = sVu[(kbase + lx) * 72 + hg * 16 + ly];
                a[1] = sVu[(kbase + lx) * 72 + hg * 16 + ly + 8];
                a[2] = sVu[(kbase + lx + 4) * 72 + hg * 16 + ly];
                a[3] = sVu[(kbase + lx + 4) * 72 + hg * 16 + ly + 8];
                mma_tf32(oacc[hg * 2 + 0], a, b0_rg0, b1_rg0);
                mma_tf32(oacc[hg * 2 + 1], a, b0_rg1, b1_rg1);
            }
        }
    }

    // ---- row sums -> inverse
    rsum0 += __shfl_xor_sync(0xffffffff, rsum0, 1);
    rsum0 += __shfl_xor_sync(0xffffffff, rsum0, 2);
    rsum1 += __shfl_xor_sync(0xffffffff, rsum1, 1);
    rsum1 += __shfl_xor_sync(0xffffffff, rsum1, 2);
    if (lx == 0) {
        sm[OS + quad * 64 + r0] = rsum0;
        sm[OS + quad * 64 + r1] = rsum1;
    }
    __syncthreads();
    if (tid < 64) {
        float s = sm[OS + tid] + sm[OS + 64 + tid] + sm[OS + 128 + tid] + sm[OS + 192 + tid];
        sm[OI + tid] = (s == 0.f) ? 1.f : (1.f / s);
    }
    __syncthreads();   // inv ready; also fences last chunk's sK/sV use

    // ---- stage partial out^T into smem: sR[quad][row][h] (stride 68)
    {
        float* sR = sm + OK_;
        #pragma unroll
        for (int hg = 0; hg < 4; hg++)
            #pragma unroll
            for (int rg = 0; rg < 2; rg++) {
                float* p = sR + quad * 4352 + (stripe * 16 + rg * 8) * 68 + hg * 16;
                p[(2 * lx) * 68 + ly]         = oacc[hg * 2 + rg][0];
                p[(2 * lx + 1) * 68 + ly]     = oacc[hg * 2 + rg][1];
                p[(2 * lx) * 68 + ly + 8]     = oacc[hg * 2 + rg][2];
                p[(2 * lx + 1) * 68 + ly + 8] = oacc[hg * 2 + rg][3];
            }
    }

    // ---- write normalized A (coalesced float4) while stage settles
    {
        int row = tid >> 3, s8 = tid & 7;
        float inv = sm[OI + row];
        float4* grow = reinterpret_cast<float4*>(Aout + ((size_t)b * NN + n0 + row) * NN);
        #pragma unroll
        for (int i = 0; i < 16; i++) {
            int c4 = s8 + 8 * i;
            float4 t = *reinterpret_cast<const float4*>(&sAf[row * 516 + 4 * c4]);
            t.x *= inv; t.y *= inv; t.z *= inv; t.w *= inv;
            grow[c4] = t;
        }
    }
    __syncthreads();

    // ---- reduce 4 quad partials, scale, write out[n,b,h]
    {
        const float* sR = sm + OK_;
        int row = tid >> 3, h0 = (tid & 7) * 8;
        float inv = sm[OI + row];
        float4 A0 = make_float4(0.f, 0.f, 0.f, 0.f);
        float4 A1 = make_float4(0.f, 0.f, 0.f, 0.f);
        #pragma unroll
        for (int qd = 0; qd < 4; qd++) {
            float4 p0 = *reinterpret_cast<const float4*>(sR + qd * 4352 + row * 68 + h0);
            float4 p1 = *reinterpret_cast<const float4*>(sR + qd * 4352 + row * 68 + h0 + 4);
            A0.x += p0.x; A0.y += p0.y; A0.z += p0.z; A0.w += p0.w;
            A1.x += p1.x; A1.y += p1.y; A1.z += p1.z; A1.w += p1.w;
        }
        A0.x *= inv; A0.y *= inv; A0.z *= inv; A0.w *= inv;
        A1.x *= inv; A1.y *= inv; A1.z *= inv; A1.w *= inv;
        float* orow = out + ((size_t)(n0 + row) * BB + b) * HH + h0;
        *reinterpret_cast<float4*>(orow)     = A0;
        *reinterpret_cast<float4*>(orow + 4) = A1;
    }
}

// ---------------------------------------------------------------------------
extern "C" void kernel_launch(void* const* d_in, const int* in_sizes, int n_in,
                              void* d_out, int out_size)
{
    const float* q    = (const float*)d_in[0];
    const float* k    = (const float*)d_in[1];
    const float* v    = (const float*)d_in[2];
    const float* mask = (const float*)d_in[3];
    const float* Wq   = (const float*)d_in[4];
    const float* bq   = (const float*)d_in[5];
    const float* Wk   = (const float*)d_in[6];
    const float* bk   = (const float*)d_in[7];
    const float* Wv   = (const float*)d_in[8];
    const float* bv   = (const float*)d_in[9];

    float* out  = (float*)d_out;                         // [N,B,H] first
    float* Aout = (float*)d_out + (size_t)NN * BB * HH;  // then [B,N,N]

    const int smem_bytes = SMEM_FLOATS * 4;
    cudaFuncSetAttribute(attn_kernel, cudaFuncAttributeMaxDynamicSharedMemorySize,
                         smem_bytes);

    proj_kernel<<<dim3((NN * BB) / 128, 3), 256>>>(q, k, v, Wq, bq, Wk, bk, Wv, bv);
    attn_kernel<<<dim3(NN / 64, BB), 512, smem_bytes>>>(mask, out, Aout);
}

// round 10
// speedup vs baseline: 1.0267x; 1.0267x over previous
#include <cuda_runtime.h>
#include <cstdint>

#define HH 64
#define NN 512
#define BB 128

__device__ float g_qp[BB * NN * HH];
__device__ float g_kp[BB * NN * HH];
__device__ float g_vp[BB * NN * HH];

// ---------------- helpers ----------------
__device__ __forceinline__ uint32_t tf32r(float f) {
    uint32_t u;
    asm("cvt.rna.tf32.f32 %0, %1;" : "=r"(u) : "f"(f));
    return u;
}
__device__ __forceinline__ void mma_tf32(float* d, const uint32_t* a,
                                         uint32_t b0, uint32_t b1) {
    asm volatile(
        "mma.sync.aligned.m16n8k8.row.col.f32.tf32.tf32.f32 "
        "{%0,%1,%2,%3}, {%4,%5,%6,%7}, {%8,%9}, {%0,%1,%2,%3};"
        : "+f"(d[0]), "+f"(d[1]), "+f"(d[2]), "+f"(d[3])
        : "r"(a[0]), "r"(a[1]), "r"(a[2]), "r"(a[3]), "r"(b0), "r"(b1));
}

// exp(s * 0.125) on FMA/ALU pipes only.
__device__ __forceinline__ float fexp8(float s) {
    float y = s * 0.18033688011112042f;      // 0.125 * log2(e)
    float z = y + 12582912.0f;               // RN to integer
    int   i = __float_as_int(z) - 0x4B400000;
    float f = y - (z - 12582912.0f);
    float p = 0.0013333558f;
    p = p * f + 0.0096181291f;
    p = p * f + 0.0555041087f;
    p = p * f + 0.2402265070f;
    p = p * f + 0.6931471806f;
    p = p * f + 1.0f;
    return __int_as_float(__float_as_int(p) + (i << 23));
}

// ---------------------------------------------------------------------------
// Projection with tf32 mma; outputs stored tf32-pre-rounded (rna).
// ---------------------------------------------------------------------------
__global__ __launch_bounds__(256, 2) void proj_kernel(
    const float* __restrict__ q, const float* __restrict__ k,
    const float* __restrict__ v,
    const float* __restrict__ Wq, const float* __restrict__ bq,
    const float* __restrict__ Wk, const float* __restrict__ bk,
    const float* __restrict__ Wv, const float* __restrict__ bv)
{
    __shared__ uint32_t sX[128 * 68];
    __shared__ uint32_t sW[64 * 68];
    __shared__ float    sB[64];

    const float* x; const float* W; const float* bias; float* dst;
    if (blockIdx.y == 0)      { x = q; W = Wq; bias = bq; dst = g_qp; }
    else if (blockIdx.y == 1) { x = k; W = Wk; bias = bk; dst = g_kp; }
    else                      { x = v; W = Wv; bias = bv; dst = g_vp; }

    const int tid  = threadIdx.x;
    const int row0 = blockIdx.x * 128;

    #pragma unroll
    for (int it = 0; it < 8; it++) {
        int idx = tid + it * 256;
        int r = idx >> 4, c4 = idx & 15;
        float4 t = *reinterpret_cast<const float4*>(x + (size_t)(row0 + r) * HH + c4 * 4);
        uint4 u = { tf32r(t.x), tf32r(t.y), tf32r(t.z), tf32r(t.w) };
        *reinterpret_cast<uint4*>(&sX[r * 68 + c4 * 4]) = u;
    }
    #pragma unroll
    for (int it = 0; it < 4; it++) {
        int idx = tid + it * 256;
        int r = idx >> 4, c4 = idx & 15;
        float4 t = *reinterpret_cast<const float4*>(W + (size_t)r * HH + c4 * 4);
        uint4 u = { tf32r(t.x), tf32r(t.y), tf32r(t.z), tf32r(t.w) };
        *reinterpret_cast<uint4*>(&sW[r * 68 + c4 * 4]) = u;
    }
    if (tid < 64) sB[tid] = bias[tid];
    __syncthreads();

    const int w    = tid >> 5;
    const int lane = tid & 31;
    const int lx   = lane & 3;
    const int ly   = lane >> 2;
    const int r0   = w * 16 + ly;
    const int r1   = r0 + 8;

    float acc[8][4];
    #pragma unroll
    for (int t = 0; t < 8; t++)
        #pragma unroll
        for (int i = 0; i < 4; i++) acc[t][i] = 0.f;

    #pragma unroll
    for (int k0 = 0; k0 < 64; k0 += 8) {
        uint32_t a[4];
        a[0] = sX[r0 * 68 + k0 + lx];
        a[1] = sX[r1 * 68 + k0 + lx];
        a[2] = sX[r0 * 68 + k0 + lx + 4];
        a[3] = sX[r1 * 68 + k0 + lx + 4];
        #pragma unroll
        for (int t = 0; t < 8; t++) {
            uint32_t b0 = sW[(t * 8 + ly) * 68 + k0 + lx];
            uint32_t b1 = sW[(t * 8 + ly) * 68 + k0 + 4 + lx];
            mma_tf32(acc[t], a, b0, b1);
        }
    }

    int g0 = row0 + r0, g1 = row0 + r1;
    float* orow0 = dst + ((size_t)(g0 & 127) * NN + (g0 >> 7)) * HH;
    float* orow1 = dst + ((size_t)(g1 & 127) * NN + (g1 >> 7)) * HH;
    #pragma unroll
    for (int t = 0; t < 8; t++) {
        int c0 = t * 8 + 2 * lx;
        float b0 = sB[c0], b1 = sB[c0 + 1];
        float2 o0 = make_float2(__uint_as_float(tf32r(acc[t][0] + b0)),
                                __uint_as_float(tf32r(acc[t][1] + b1)));
        float2 o1 = make_float2(__uint_as_float(tf32r(acc[t][2] + b0)),
                                __uint_as_float(tf32r(acc[t][3] + b1)));
        *reinterpret_cast<float2*>(orow0 + c0) = o0;
        *reinterpret_cast<float2*>(orow1 + c0) = o1;
    }
}

// ---------------------------------------------------------------------------
// Attention: CTA = 32 n-rows x one batch, 256 threads (8 warps =
// 2 row-stripes x 4 key-quads), 4 chunks of 128 keys, NO resident e-tile.
// e written unnormalized to Aout during the loop; renormalized in-place
// from L2 after rowsums. AV via out^T = V^T e^T (shuffle-built B-frags,
// warp-local). 2 CTAs/SM (smem 81KB, regs <= 128).
// ---------------------------------------------------------------------------
// smem float offsets
#define OQ   0                      // 32 x 68
#define OK_  2176                   // 128 x 68 (reused as out^T stage 4x32x68)
#define OV   10880                  // 128 x 72
#define OS   20096                  // 128 partial row sums (4 quads x 32)
#define OI   20224                  // 32 inverse sums
#define SMEM_FLOATS 20256

__global__ __launch_bounds__(256, 2) void attn_kernel(
    const float* __restrict__ mask,
    float* __restrict__ out,     // [N,B,H]
    float* __restrict__ Aout)    // [B,N,N]
{
    extern __shared__ float sm[];
    uint32_t* sQu = reinterpret_cast<uint32_t*>(sm + OQ);
    uint32_t* sKu = reinterpret_cast<uint32_t*>(sm + OK_);
    uint32_t* sVu = reinterpret_cast<uint32_t*>(sm + OV);

    const int tid  = threadIdx.x;
    const int w    = tid >> 5;
    const int lane = tid & 31;
    const int lx   = lane & 3;
    const int ly   = lane >> 2;
    const int stripe = w & 1;        // 16-row stripe (0..1)
    const int quad   = w >> 1;       // key group (0..3)
    const int r0 = stripe * 16 + ly, r1 = r0 + 8;

    const int n0 = blockIdx.x * 32;
    const int b  = blockIdx.y;

    const float* qp = g_qp + (size_t)b * NN * HH;
    const float* kp = g_kp + (size_t)b * NN * HH;
    const float* vp = g_vp + (size_t)b * NN * HH;
    const float* mbase = mask + ((size_t)b * NN + n0) * NN;
    float* Ab = Aout + ((size_t)b * NN + n0) * NN;

    // shuffle source lanes for e^T B-frag construction
    const int l0 = ly * 4 + (lx >> 1);
    const int l1 = l0 + 2;
    const bool oddx = (lx & 1);

    // ---- Q tile (32 x 64), already tf32-rounded by proj
    #pragma unroll
    for (int it = 0; it < 2; it++) {
        int idx = tid + it * 256;
        int r = idx >> 4, c4 = idx & 15;
        float4 t = *reinterpret_cast<const float4*>(qp + (size_t)(n0 + r) * HH + c4 * 4);
        *reinterpret_cast<float4*>(&sm[OQ + r * 68 + c4 * 4]) = t;
    }
    __syncthreads();

    // ---- Q fragments hoisted
    uint32_t qf[8][4];
    #pragma unroll
    for (int kk = 0; kk < 8; kk++) {
        int k0 = kk * 8;
        qf[kk][0] = sQu[r0 * 68 + k0 + lx];
        qf[kk][1] = sQu[r1 * 68 + k0 + lx];
        qf[kk][2] = sQu[r0 * 68 + k0 + lx + 4];
        qf[kk][3] = sQu[r1 * 68 + k0 + lx + 4];
    }

    // out^T partial accumulators: [hg 0..3][rg 0..1]
    float oacc[8][4];
    #pragma unroll
    for (int t = 0; t < 8; t++)
        #pragma unroll
        for (int i = 0; i < 4; i++) oacc[t][i] = 0.f;
    float rsum0 = 0.f, rsum1 = 0.f;

    for (int c = 0; c < 4; c++) {
        const int mt = c * 128;
        __syncthreads();   // all warps done with prev sK/sV

        // ---- load K/V chunk (128 x 64 each)
        #pragma unroll
        for (int it = 0; it < 8; it++) {
            int idx = tid + it * 256;
            int r = idx >> 4, c4 = idx & 15;
            float4 t = *reinterpret_cast<const float4*>(kp + (size_t)(mt + r) * HH + c4 * 4);
            *reinterpret_cast<float4*>(&sm[OK_ + r * 68 + c4 * 4]) = t;
            float4 s = *reinterpret_cast<const float4*>(vp + (size_t)(mt + r) * HH + c4 * 4);
            *reinterpret_cast<float4*>(&sm[OV + r * 72 + c4 * 4]) = s;
        }
        __syncthreads();

        // ---- mask loads early (latency covered by S-MMA)
        float2 m0[4], m1[4];
        #pragma unroll
        for (int t = 0; t < 4; t++) {
            int gc = mt + quad * 32 + t * 8 + 2 * lx;
            m0[t] = *reinterpret_cast<const float2*>(mbase + (size_t)r0 * NN + gc);
            m1[t] = *reinterpret_cast<const float2*>(mbase + (size_t)r1 * NN + gc);
        }

        // ---- S = Q K^T : 16 rows x 32 keys per warp
        float sacc[4][4];
        #pragma unroll
        for (int t = 0; t < 4; t++)
            #pragma unroll
            for (int i = 0; i < 4; i++) sacc[t][i] = 0.f;

        #pragma unroll
        for (int kk = 0; kk < 8; kk++) {
            int k0 = kk * 8;
            #pragma unroll
            for (int t = 0; t < 4; t++) {
                int key = quad * 32 + t * 8 + ly;
                uint32_t b0 = sKu[key * 68 + k0 + lx];
                uint32_t b1 = sKu[key * 68 + k0 + 4 + lx];
                mma_tf32(sacc[t], qf[kk], b0, b1);
            }
        }

        // ---- e = exp(S/8)*mask ; rowsums ; write UNNORMALIZED e to Aout
        #pragma unroll
        for (int t = 0; t < 4; t++) {
            int gc = mt + quad * 32 + t * 8 + 2 * lx;
            float e00 = fexp8(sacc[t][0]) * m0[t].x;
            float e01 = fexp8(sacc[t][1]) * m0[t].y;
            float e10 = fexp8(sacc[t][2]) * m1[t].x;
            float e11 = fexp8(sacc[t][3]) * m1[t].y;
            rsum0 += e00 + e01;
            rsum1 += e10 + e11;
            *reinterpret_cast<float2*>(Ab + (size_t)r0 * NN + gc) = make_float2(e00, e01);
            *reinterpret_cast<float2*>(Ab + (size_t)r1 * NN + gc) = make_float2(e10, e11);
            // rna-rounded copies for the AV MMA
            sacc[t][0] = __uint_as_float(tf32r(e00));
            sacc[t][1] = __uint_as_float(tf32r(e01));
            sacc[t][2] = __uint_as_float(tf32r(e10));
            sacc[t][3] = __uint_as_float(tf32r(e11));
        }

        // ---- AV: out^T += V^T e^T, warp-local (no barrier)
        #pragma unroll
        for (int kt = 0; kt < 4; kt++) {
            float t00 = __shfl_sync(0xffffffffu, sacc[kt][0], l0);
            float t01 = __shfl_sync(0xffffffffu, sacc[kt][1], l0);
            float t10 = __shfl_sync(0xffffffffu, sacc[kt][0], l1);
            float t11 = __shfl_sync(0xffffffffu, sacc[kt][1], l1);
            uint32_t b0_rg0 = __float_as_uint(oddx ? t01 : t00);
            uint32_t b1_rg0 = __float_as_uint(oddx ? t11 : t10);
            float u00 = __shfl_sync(0xffffffffu, sacc[kt][2], l0);
            float u01 = __shfl_sync(0xffffffffu, sacc[kt][3], l0);
            float u10 = __shfl_sync(0xffffffffu, sacc[kt][2], l1);
            float u11 = __shfl_sync(0xffffffffu, sacc[kt][3], l1);
            uint32_t b0_rg1 = __float_as_uint(oddx ? u01 : u00);
            uint32_t b1_rg1 = __float_as_uint(oddx ? u11 : u10);

            const int kbase = quad * 32 + kt * 8;
            #pragma unroll
            for (int hg = 0; hg < 4; hg++) {
                uint32_t a[4];
                a[0] = sVu[(kbase + lx) * 72 + hg * 16 + ly];
                a[1] = sVu[(kbase + lx) * 72 + hg * 16 + ly + 8];
                a[2] = sVu[(kbase + lx + 4) * 72 + hg * 16 + ly];
                a[3] = sVu[(kbase + lx + 4) * 72 + hg * 16 + ly + 8];
                mma_tf32(oacc[hg * 2 + 0], a, b0_rg0, b1_rg0);
                mma_tf32(oacc[hg * 2 + 1], a, b0_rg1, b1_rg1);
            }
        }
    }

    // ---- row sums -> inverse
    rsum0 += __shfl_xor_sync(0xffffffff, rsum0, 1);
    rsum0 += __shfl_xor_sync(0xffffffff, rsum0, 2);
    rsum1 += __shfl_xor_sync(0xffffffff, rsum1, 1);
    rsum1 += __shfl_xor_sync(0xffffffff, rsum1, 2);
    if (lx == 0) {
        sm[OS + quad * 32 + r0] = rsum0;
        sm[OS + quad * 32 + r1] = rsum1;
    }
    __syncthreads();
    if (tid < 32) {
        float s = sm[OS + tid] + sm[OS + 32 + tid] + sm[OS + 64 + tid] + sm[OS + 96 + tid];
        sm[OI + tid] = (s == 0.f) ? 1.f : (1.f / s);
    }
    __syncthreads();   // inv ready; also orders the e global writes CTA-wide

    // ---- stage partial out^T into smem (reuse sK region)
    {
        float* sR = sm + OK_;
        #pragma unroll
        for (int hg = 0; hg < 4; hg++)
            #pragma unroll
            for (int rg = 0; rg < 2; rg++) {
                float* p = sR + quad * 2176 + (stripe * 16 + rg * 8) * 68 + hg * 16;
                p[(2 * lx) * 68 + ly]         = oacc[hg * 2 + rg][0];
                p[(2 * lx + 1) * 68 + ly]     = oacc[hg * 2 + rg][1];
                p[(2 * lx) * 68 + ly + 8]     = oacc[hg * 2 + rg][2];
                p[(2 * lx + 1) * 68 + ly + 8] = oacc[hg * 2 + rg][3];
            }
    }

    // ---- renormalize A in place (strip is L2-resident), coalesced float4
    #pragma unroll
    for (int it = 0; it < 16; it++) {
        int idx = tid + it * 256;       // 0..4095 over 32 rows x 128 float4
        int row = idx >> 7, c4 = idx & 127;
        float inv = sm[OI + row];
        float4* p = reinterpret_cast<float4*>(Ab + (size_t)row * NN) + c4;
        float4 t = *p;
        t.x *= inv; t.y *= inv; t.z *= inv; t.w *= inv;
        *p = t;
    }
    __syncthreads();

    // ---- reduce 4 quad partials, scale, write out[n,b,h]
    {
        const float* sR = sm + OK_;
        int row = tid >> 3, h0 = (tid & 7) * 8;
        float inv = sm[OI + row];
        float4 A0 = make_float4(0.f, 0.f, 0.f, 0.f);
        float4 A1 = make_float4(0.f, 0.f, 0.f, 0.f);
        #pragma unroll
        for (int qd = 0; qd < 4; qd++) {
            float4 p0 = *reinterpret_cast<const float4*>(sR + qd * 2176 + row * 68 + h0);
            float4 p1 = *reinterpret_cast<const float4*>(sR + qd * 2176 + row * 68 + h0 + 4);
            A0.x += p0.x; A0.y += p0.y; A0.z += p0.z; A0.w += p0.w;
            A1.x += p1.x; A1.y += p1.y; A1.z += p1.z; A1.w += p1.w;
        }
        A0.x *= inv; A0.y *= inv; A0.z *= inv; A0.w *= inv;
        A1.x *= inv; A1.y *= inv; A1.z *= inv; A1.w *= inv;
        float* orow = out + ((size_t)(n0 + row) * BB + b) * HH + h0;
        *reinterpret_cast<float4*>(orow)     = A0;
        *reinterpret_cast<float4*>(orow + 4) = A1;
    }
}

// ---------------------------------------------------------------------------
extern "C" void kernel_launch(void* const* d_in, const int* in_sizes, int n_in,
                              void* d_out, int out_size)
{
    const float* q    = (const float*)d_in[0];
    const float* k    = (const float*)d_in[1];
    const float* v    = (const float*)d_in[2];
    const float* mask = (const float*)d_in[3];
    const float* Wq   = (const float*)d_in[4];
    const float* bq   = (const float*)d_in[5];
    const float* Wk   = (const float*)d_in[6];
    const float* bk   = (const float*)d_in[7];
    const float* Wv   = (const float*)d_in[8];
    const float* bv   = (const float*)d_in[9];

    float* out  = (float*)d_out;                         // [N,B,H] first
    float* Aout = (float*)d_out + (size_t)NN * BB * HH;  // then [B,N,N]

    const int smem_bytes = SMEM_FLOATS * 4;
    cudaFuncSetAttribute(attn_kernel, cudaFuncAttributeMaxDynamicSharedMemorySize,
                         smem_bytes);

    proj_kernel<<<dim3((NN * BB) / 128, 3), 256>>>(q, k, v, Wq, bq, Wk, bk, Wv, bv);
    attn_kernel<<<dim3(NN / 32, BB), 256, smem_bytes>>>(mask, out, Aout);
}